// round 5
// baseline (speedup 1.0000x reference)
#include <cuda_runtime.h>
#include <cuda_bf16.h>
#include <math.h>

typedef unsigned long long ull;

// ---------------- scratch (static device globals; no allocation) ----------------
__device__ float g_pre[2u * 512u * 32u * 512u];   // [dir][t][b][c] 64MB
__device__ float g_hs[512u * 32u * 1024u];        // [t][b][dir*512+c] 64MB

// ---------------- f32x2 helpers ----------------
__device__ __forceinline__ ull ffma2(ull a, ull b, ull c) {
    ull d;
    asm("fma.rn.f32x2 %0, %1, %2, %3;" : "=l"(d) : "l"(a), "l"(b), "l"(c));
    return d;
}
__device__ __forceinline__ ull pack2(float x) {
    ull d;
    asm("mov.b64 %0, {%1, %1};" : "=l"(d) : "f"(x));
    return d;
}
__device__ __forceinline__ ull packab(float a, float b) {
    ull d;
    asm("mov.b64 %0, {%1, %2};" : "=l"(d) : "f"(a), "f"(b));
    return d;
}
__device__ __forceinline__ float2 unpack2(ull v) {
    float2 r;
    asm("mov.b64 {%0, %1}, %2;" : "=f"(r.x), "=f"(r.y) : "l"(v));
    return r;
}

// B smem slot for column n in [0,128): j-grouped duplicated-pair layout
// reader: thread tx reads bd[j] at slot j*16+tx  (LDS.64, conflict-free broadcast)
__device__ __forceinline__ int bslot(int n) { return (n & 7) * 16 + (n >> 3); }

// =================================================================================
// Kernel 1: pre-projection GEMM (double-buffered, duplicated-B smem)
// =================================================================================
__global__ __launch_bounds__(256, 2) void pre_gemm(
    const float* __restrict__ X,
    const float* __restrict__ Wf, const float* __restrict__ bf,
    const float* __restrict__ Wb, const float* __restrict__ bb)
{
    __shared__ float As[2][8][132];
    __shared__ ull   Bsd[2][8][129];

    const int tid = threadIdx.x;
    const int m0 = blockIdx.y * 128;
    const int n0 = blockIdx.x * 128;
    const int dir = n0 >> 9;
    const int c0 = n0 & 511;
    const float* Bmat = dir ? Wb : Wf;
    const float* bias = dir ? bb : bf;

    const int ar  = tid >> 1;
    const int akq = (tid & 1) * 4;
    const int am  = m0 + ar;
    const float* Arow = X + ((size_t)(am & 31) * 512 + (size_t)(am >> 5)) * 512;

    const int bkk = tid >> 5;
    const int bnq = (tid & 31) * 4;

    const int ty = tid >> 4;
    const int tx = tid & 15;

    ull acc[4][8];
    #pragma unroll
    for (int i = 0; i < 4; ++i)
        #pragma unroll
        for (int j = 0; j < 8; ++j) acc[i][j] = 0ull;

    // prologue: fill buffer 0
    {
        float4 av = *(const float4*)(Arow + akq);
        float4 bv = *(const float4*)(Bmat + (size_t)bkk * 512 + c0 + bnq);
        As[0][akq + 0][ar] = av.x;
        As[0][akq + 1][ar] = av.y;
        As[0][akq + 2][ar] = av.z;
        As[0][akq + 3][ar] = av.w;
        Bsd[0][bkk][bslot(bnq + 0)] = pack2(bv.x);
        Bsd[0][bkk][bslot(bnq + 1)] = pack2(bv.y);
        Bsd[0][bkk][bslot(bnq + 2)] = pack2(bv.z);
        Bsd[0][bkk][bslot(bnq + 3)] = pack2(bv.w);
    }
    __syncthreads();

    int buf = 0;
    for (int k0 = 0; k0 < 512; k0 += 8) {
        float4 av, bv;
        const bool more = (k0 + 8 < 512);
        if (more) {
            av = *(const float4*)(Arow + k0 + 8 + akq);
            bv = *(const float4*)(Bmat + (size_t)(k0 + 8 + bkk) * 512 + c0 + bnq);
        }

        #pragma unroll
        for (int k = 0; k < 8; ++k) {
            ulonglong2 a01 = *(const ulonglong2*)&As[buf][k][ty * 8];
            ulonglong2 a23 = *(const ulonglong2*)&As[buf][k][ty * 8 + 4];
            #pragma unroll
            for (int j = 0; j < 8; ++j) {
                ull bd = Bsd[buf][k][j * 16 + tx];
                acc[0][j] = ffma2(a01.x, bd, acc[0][j]);
                acc[1][j] = ffma2(a01.y, bd, acc[1][j]);
                acc[2][j] = ffma2(a23.x, bd, acc[2][j]);
                acc[3][j] = ffma2(a23.y, bd, acc[3][j]);
            }
        }

        if (more) {
            int nb = buf ^ 1;
            As[nb][akq + 0][ar] = av.x;
            As[nb][akq + 1][ar] = av.y;
            As[nb][akq + 2][ar] = av.z;
            As[nb][akq + 3][ar] = av.w;
            Bsd[nb][bkk][bslot(bnq + 0)] = pack2(bv.x);
            Bsd[nb][bkk][bslot(bnq + 1)] = pack2(bv.y);
            Bsd[nb][bkk][bslot(bnq + 2)] = pack2(bv.z);
            Bsd[nb][bkk][bslot(bnq + 3)] = pack2(bv.w);
            __syncthreads();
            buf = nb;
        }
    }

    // micro-tile column j maps to global col tx*8+j
    const int cg = c0 + tx * 8;
    float4 bl = *(const float4*)(bias + cg);
    float4 bh = *(const float4*)(bias + cg + 4);
    #pragma unroll
    for (int mp = 0; mp < 4; ++mp) {
        float2 v[8];
        #pragma unroll
        for (int j = 0; j < 8; ++j) v[j] = unpack2(acc[mp][j]);
        #pragma unroll
        for (int p = 0; p < 2; ++p) {
            int m = m0 + ty * 8 + mp * 2 + p;
            int tt = m >> 5, bb2 = m & 31;
            float* dst = g_pre + ((size_t)dir * 512 + tt) * 16384 + (size_t)bb2 * 512 + cg;
            float4 o0, o1;
            o0.x = (p ? v[0].y : v[0].x) + bl.x;
            o0.y = (p ? v[1].y : v[1].x) + bl.y;
            o0.z = (p ? v[2].y : v[2].x) + bl.z;
            o0.w = (p ? v[3].y : v[3].x) + bl.w;
            o1.x = (p ? v[4].y : v[4].x) + bh.x;
            o1.y = (p ? v[5].y : v[5].x) + bh.y;
            o1.z = (p ? v[6].y : v[6].x) + bh.z;
            o1.w = (p ? v[7].y : v[7].x) + bh.w;
            *(float4*)dst = o0;
            *(float4*)(dst + 4) = o1;
        }
    }
}

// =================================================================================
// Kernel 2: persistent bidirectional recurrence (v5 — CTA clusters)
//   128 CTAs = 16 clusters of 8. Cluster = (dir, group of 4 batches).
//   CTA rank within cluster = col slice of 64. 512 threads: (c 0..63, ks 0..7),
//   Wh[ks*64..+63][c0+c] in 32 f32x2 regs; per step stage 8KB h (4 rows), compute,
//   8-way reduce, tanh, store; hardware cluster barrier (arrive/wait split, with
//   next-step pre load issued between them).
// =================================================================================
__global__ __launch_bounds__(512) void recur_kernel(
    const float* __restrict__ Wf, const float* __restrict__ Wb)
{
    __shared__ float s_h[4 * 520];      // [4 batches][512+8]
    __shared__ float s_red[8 * 256];    // [ks][b*64+c]

    const int tid = threadIdx.x;
    const int bx  = blockIdx.x;
    const int cid = bx >> 3;                // cluster 0..15
    const int dir = cid & 1;
    const int grp = cid >> 1;               // 0..7 (4 batches each)
    const int sl  = bx & 7;                 // col slice 0..7
    const int c0  = sl * 64;
    const int bgl = grp * 4;
    const float* W = dir ? Wb : Wf;

    const int c  = tid & 63;                // col within slice
    const int ks = tid >> 6;                // k-split 0..7 (k = ks*64..+63)

    // Wh column (c0+c), k in [ks*64, ks*64+64) -> 32 f32x2 regs
    ull wreg[16][2];
    #pragma unroll
    for (int j = 0; j < 16; ++j) {
        int k = ks * 64 + j * 4;
        const float* wp = W + (size_t)(512 + k) * 512 + c0 + c;
        wreg[j][0] = packab(wp[0],    wp[512]);
        wreg[j][1] = packab(wp[1024], wp[1536]);
    }

    // staging: 512 float4s, one per thread
    const int sb   = tid >> 7;              // batch row 0..3
    const int soff = (tid & 127) * 4;       // float offset in 512-row

    // reduce/store map (tid < 256): batch rb, col rc
    const int rb = tid >> 6;
    const int rc = tid & 63;

    // first step's pre-activation
    float pre = 0.f;
    {
        const int t0 = dir ? 511 : 0;
        if (tid < 256)
            pre = __ldcg(&g_pre[((size_t)dir * 512 + t0) * 16384 +
                                (size_t)(bgl + rb) * 512 + c0 + rc]);
    }

    for (int s = 0; s < 512; ++s) {
        const int t = dir ? (511 - s) : s;

        float hval = 0.f;
        if (s == 0) {
            if (tid < 256) hval = tanhf(pre);
        } else {
            const int tp = dir ? (t + 1) : (t - 1);
            const float* hbase = g_hs + (size_t)tp * 32 * 1024 +
                                 (size_t)bgl * 1024 + dir * 512;

            // stage the group's 4 h rows (8KB) in one shot
            float4 v0 = __ldcg((const float4*)(hbase + sb * 1024 + soff));
            *(float4*)&s_h[sb * 520 + soff] = v0;
            __syncthreads();

            // mat-vec partials: smem reads warp-broadcast (address = f(b,ks) only)
            ull acc[4];
            #pragma unroll
            for (int b = 0; b < 4; ++b) acc[b] = 0ull;
            #pragma unroll
            for (int b = 0; b < 4; ++b) {
                const ulonglong2* hp = (const ulonglong2*)&s_h[b * 520 + ks * 64];
                #pragma unroll
                for (int j = 0; j < 16; ++j) {
                    ulonglong2 h2 = hp[j];
                    acc[b] = ffma2(h2.x, wreg[j][0], acc[b]);
                    acc[b] = ffma2(h2.y, wreg[j][1], acc[b]);
                }
            }
            #pragma unroll
            for (int b = 0; b < 4; ++b) {
                float2 p = unpack2(acc[b]);
                s_red[ks * 256 + b * 64 + c] = p.x + p.y;
            }
            __syncthreads();

            if (tid < 256) {
                float sum = pre;
                #pragma unroll
                for (int k8 = 0; k8 < 8; ++k8) sum += s_red[k8 * 256 + tid];
                hval = tanhf(sum);
            }
        }

        if (tid < 256)
            __stcg(&g_hs[((size_t)t * 32 + bgl + rb) * 1024 +
                         dir * 512 + c0 + rc], hval);

        if (s < 511) {
            // each thread's own h store is released by its own arrive
            asm volatile("barrier.cluster.arrive.release.aligned;" ::: "memory");
            // hide next step's pre load under the barrier wait
            const int tn = dir ? (510 - s) : (s + 1);
            if (tid < 256)
                pre = __ldcg(&g_pre[((size_t)dir * 512 + tn) * 16384 +
                                    (size_t)(bgl + rb) * 512 + c0 + rc]);
            asm volatile("barrier.cluster.wait.acquire.aligned;" ::: "memory");
        }
    }
}

// =================================================================================
// Kernel 3: output GEMM (double-buffered, duplicated-B smem)
// =================================================================================
__global__ __launch_bounds__(256, 2) void out_gemm(
    const float* __restrict__ Wo, const float* __restrict__ bo,
    float* __restrict__ out)
{
    __shared__ float As[2][8][132];
    __shared__ ull   Bsd[2][8][129];

    const int tid = threadIdx.x;
    const int m0 = blockIdx.y * 128;
    const int n0 = blockIdx.x * 128;

    const int ar  = tid >> 1;
    const int akq = (tid & 1) * 4;
    const float* Arow = g_hs + (size_t)(m0 + ar) * 1024;

    const int bkk = tid >> 5;
    const int bnq = (tid & 31) * 4;

    const int ty = tid >> 4;
    const int tx = tid & 15;

    ull acc[4][8];
    #pragma unroll
    for (int i = 0; i < 4; ++i)
        #pragma unroll
        for (int j = 0; j < 8; ++j) acc[i][j] = 0ull;

    {
        float4 av = *(const float4*)(Arow + akq);
        float4 bv = *(const float4*)(Wo + (size_t)bkk * 512 + n0 + bnq);
        As[0][akq + 0][ar] = av.x;
        As[0][akq + 1][ar] = av.y;
        As[0][akq + 2][ar] = av.z;
        As[0][akq + 3][ar] = av.w;
        Bsd[0][bkk][bslot(bnq + 0)] = pack2(bv.x);
        Bsd[0][bkk][bslot(bnq + 1)] = pack2(bv.y);
        Bsd[0][bkk][bslot(bnq + 2)] = pack2(bv.z);
        Bsd[0][bkk][bslot(bnq + 3)] = pack2(bv.w);
    }
    __syncthreads();

    int buf = 0;
    for (int k0 = 0; k0 < 1024; k0 += 8) {
        float4 av, bv;
        const bool more = (k0 + 8 < 1024);
        if (more) {
            av = *(const float4*)(Arow + k0 + 8 + akq);
            bv = *(const float4*)(Wo + (size_t)(k0 + 8 + bkk) * 512 + n0 + bnq);
        }

        #pragma unroll
        for (int k = 0; k < 8; ++k) {
            ulonglong2 a01 = *(const ulonglong2*)&As[buf][k][ty * 8];
            ulonglong2 a23 = *(const ulonglong2*)&As[buf][k][ty * 8 + 4];
            #pragma unroll
            for (int j = 0; j < 8; ++j) {
                ull bd = Bsd[buf][k][j * 16 + tx];
                acc[0][j] = ffma2(a01.x, bd, acc[0][j]);
                acc[1][j] = ffma2(a01.y, bd, acc[1][j]);
                acc[2][j] = ffma2(a23.x, bd, acc[2][j]);
                acc[3][j] = ffma2(a23.y, bd, acc[3][j]);
            }
        }

        if (more) {
            int nb = buf ^ 1;
            As[nb][akq + 0][ar] = av.x;
            As[nb][akq + 1][ar] = av.y;
            As[nb][akq + 2][ar] = av.z;
            As[nb][akq + 3][ar] = av.w;
            Bsd[nb][bkk][bslot(bnq + 0)] = pack2(bv.x);
            Bsd[nb][bkk][bslot(bnq + 1)] = pack2(bv.y);
            Bsd[nb][bkk][bslot(bnq + 2)] = pack2(bv.z);
            Bsd[nb][bkk][bslot(bnq + 3)] = pack2(bv.w);
            __syncthreads();
            buf = nb;
        }
    }

    const int og = n0 + tx * 8;
    float4 bl = *(const float4*)(bo + og);
    float4 bh = *(const float4*)(bo + og + 4);
    #pragma unroll
    for (int mp = 0; mp < 4; ++mp) {
        float2 v[8];
        #pragma unroll
        for (int j = 0; j < 8; ++j) v[j] = unpack2(acc[mp][j]);
        #pragma unroll
        for (int p = 0; p < 2; ++p) {
            int m = m0 + ty * 8 + mp * 2 + p;
            int tt = m >> 5, bb2 = m & 31;
            float* dst = out + ((size_t)bb2 * 512 + tt) * 512 + og;
            float4 o0, o1;
            o0.x = (p ? v[0].y : v[0].x) + bl.x;
            o0.y = (p ? v[1].y : v[1].x) + bl.y;
            o0.z = (p ? v[2].y : v[2].x) + bl.z;
            o0.w = (p ? v[3].y : v[3].x) + bl.w;
            o1.x = (p ? v[4].y : v[4].x) + bh.x;
            o1.y = (p ? v[5].y : v[5].x) + bh.y;
            o1.z = (p ? v[6].y : v[6].x) + bh.z;
            o1.w = (p ? v[7].y : v[7].x) + bh.w;
            *(float4*)dst = o0;
            *(float4*)(dst + 4) = o1;
        }
    }
}

// =================================================================================
extern "C" void kernel_launch(void* const* d_in, const int* in_sizes, int n_in,
                              void* d_out, int out_size)
{
    const float* X  = (const float*)d_in[0];
    const float* Wf = (const float*)d_in[1];
    const float* bf = (const float*)d_in[2];
    const float* Wb = (const float*)d_in[3];
    const float* bb = (const float*)d_in[4];
    const float* Wo = (const float*)d_in[5];
    const float* bo = (const float*)d_in[6];
    float* out = (float*)d_out;

    pre_gemm<<<dim3(8, 128), 256>>>(X, Wf, bf, Wb, bb);

    // recurrence: 128 CTAs in clusters of 8 (portable size)
    {
        cudaLaunchConfig_t cfg = {};
        cfg.gridDim  = dim3(128, 1, 1);
        cfg.blockDim = dim3(512, 1, 1);
        cfg.dynamicSmemBytes = 0;
        cudaLaunchAttribute attrs[1];
        attrs[0].id = cudaLaunchAttributeClusterDimension;
        attrs[0].val.clusterDim = {8, 1, 1};
        cfg.attrs = attrs;
        cfg.numAttrs = 1;
        cudaLaunchKernelEx(&cfg, recur_kernel, Wf, Wb);
    }

    out_gemm<<<dim3(4, 128), 256>>>(Wo, bo, out);
}

// round 6
// speedup vs baseline: 1.5090x; 1.5090x over previous
#include <cuda_runtime.h>
#include <cuda_bf16.h>
#include <math.h>

typedef unsigned long long ull;

// ---------------- scratch (static device globals; no allocation) ----------------
__device__ float g_pre[2u * 512u * 32u * 512u];   // [dir][t][b][c] 64MB
__device__ float g_hs[512u * 32u * 1024u];        // [t][b][dir*512+c] 64MB
__device__ unsigned int g_bar[16 * 32];           // 16 counters, 128B apart

// ---------------- f32x2 helpers ----------------
__device__ __forceinline__ ull ffma2(ull a, ull b, ull c) {
    ull d;
    asm("fma.rn.f32x2 %0, %1, %2, %3;" : "=l"(d) : "l"(a), "l"(b), "l"(c));
    return d;
}
__device__ __forceinline__ ull pack2(float x) {
    ull d;
    asm("mov.b64 %0, {%1, %1};" : "=l"(d) : "f"(x));
    return d;
}
__device__ __forceinline__ ull packab(float a, float b) {
    ull d;
    asm("mov.b64 %0, {%1, %2};" : "=l"(d) : "f"(a), "f"(b));
    return d;
}
__device__ __forceinline__ float2 unpack2(ull v) {
    float2 r;
    asm("mov.b64 {%0, %1}, %2;" : "=f"(r.x), "=f"(r.y) : "l"(v));
    return r;
}

// =================================================================================
// Kernel 1: pre-projection GEMM (R4 version: double-buffered smem)
// =================================================================================
__global__ __launch_bounds__(256) void pre_gemm(
    const float* __restrict__ X,
    const float* __restrict__ Wf, const float* __restrict__ bf,
    const float* __restrict__ Wb, const float* __restrict__ bb)
{
    __shared__ float As[2][8][132];
    __shared__ float Bs[2][8][136];

    if (blockIdx.x == 0 && blockIdx.y == 0 && threadIdx.x < 16)
        g_bar[threadIdx.x * 32] = 0u;

    const int tid = threadIdx.x;
    const int m0 = blockIdx.y * 128;
    const int n0 = blockIdx.x * 128;
    const int dir = n0 >> 9;
    const int c0 = n0 & 511;
    const float* Bmat = dir ? Wb : Wf;
    const float* bias = dir ? bb : bf;

    const int ar  = tid >> 1;
    const int akq = (tid & 1) * 4;
    const int am  = m0 + ar;
    const float* Arow = X + ((size_t)(am & 31) * 512 + (size_t)(am >> 5)) * 512;

    const int bkk = tid >> 5;
    const int bnq = (tid & 31) * 4;

    const int ty = tid >> 4;
    const int tx = tid & 15;

    ull acc[4][8];
    #pragma unroll
    for (int i = 0; i < 4; ++i)
        #pragma unroll
        for (int j = 0; j < 8; ++j) acc[i][j] = 0ull;

    {
        float4 av = *(const float4*)(Arow + akq);
        float4 bv = *(const float4*)(Bmat + (size_t)bkk * 512 + c0 + bnq);
        As[0][akq + 0][ar] = av.x;
        As[0][akq + 1][ar] = av.y;
        As[0][akq + 2][ar] = av.z;
        As[0][akq + 3][ar] = av.w;
        *(float4*)&Bs[0][bkk][bnq] = bv;
    }
    __syncthreads();

    int buf = 0;
    for (int k0 = 0; k0 < 512; k0 += 8) {
        float4 av, bv;
        const bool more = (k0 + 8 < 512);
        if (more) {
            av = *(const float4*)(Arow + k0 + 8 + akq);
            bv = *(const float4*)(Bmat + (size_t)(k0 + 8 + bkk) * 512 + c0 + bnq);
        }

        #pragma unroll
        for (int k = 0; k < 8; ++k) {
            ulonglong2 a01 = *(const ulonglong2*)&As[buf][k][ty * 8];
            ulonglong2 a23 = *(const ulonglong2*)&As[buf][k][ty * 8 + 4];
            float4 bA = *(const float4*)&Bs[buf][k][tx * 8];
            float4 bB = *(const float4*)&Bs[buf][k][tx * 8 + 4];
            ull bd[8];
            bd[0] = pack2(bA.x); bd[1] = pack2(bA.y);
            bd[2] = pack2(bA.z); bd[3] = pack2(bA.w);
            bd[4] = pack2(bB.x); bd[5] = pack2(bB.y);
            bd[6] = pack2(bB.z); bd[7] = pack2(bB.w);
            #pragma unroll
            for (int j = 0; j < 8; ++j) {
                acc[0][j] = ffma2(a01.x, bd[j], acc[0][j]);
                acc[1][j] = ffma2(a01.y, bd[j], acc[1][j]);
                acc[2][j] = ffma2(a23.x, bd[j], acc[2][j]);
                acc[3][j] = ffma2(a23.y, bd[j], acc[3][j]);
            }
        }

        if (more) {
            int nb = buf ^ 1;
            As[nb][akq + 0][ar] = av.x;
            As[nb][akq + 1][ar] = av.y;
            As[nb][akq + 2][ar] = av.z;
            As[nb][akq + 3][ar] = av.w;
            *(float4*)&Bs[nb][bkk][bnq] = bv;
            __syncthreads();
            buf = nb;
        }
    }

    const int cg = c0 + tx * 8;
    float4 bl = *(const float4*)(bias + cg);
    float4 bh = *(const float4*)(bias + cg + 4);
    #pragma unroll
    for (int mp = 0; mp < 4; ++mp) {
        float2 v[8];
        #pragma unroll
        for (int j = 0; j < 8; ++j) v[j] = unpack2(acc[mp][j]);
        #pragma unroll
        for (int p = 0; p < 2; ++p) {
            int m = m0 + ty * 8 + mp * 2 + p;
            int tt = m >> 5, bb2 = m & 31;
            float* dst = g_pre + ((size_t)dir * 512 + tt) * 16384 + (size_t)bb2 * 512 + cg;
            float4 o0, o1;
            o0.x = (p ? v[0].y : v[0].x) + bl.x;
            o0.y = (p ? v[1].y : v[1].x) + bl.y;
            o0.z = (p ? v[2].y : v[2].x) + bl.z;
            o0.w = (p ? v[3].y : v[3].x) + bl.w;
            o1.x = (p ? v[4].y : v[4].x) + bh.x;
            o1.y = (p ? v[5].y : v[5].x) + bh.y;
            o1.z = (p ? v[6].y : v[6].x) + bh.z;
            o1.w = (p ? v[7].y : v[7].x) + bh.w;
            *(float4*)dst = o0;
            *(float4*)(dst + 4) = o1;
        }
    }
}

// =================================================================================
// Kernel 2: persistent bidirectional recurrence (v6)
//   128 CTAs = 2 dirs x 8 batch-groups(4) x 8 col-slices(64), 512 threads.
//   Thread = (c 0..63, ks 0..7): Wh[ks*64..+63][c0+c] in 32 f32x2 regs.
//   Per step: stage 8KB h (4 rows, 1 float4/thread), compute, 8-way reduce,
//   tanh, store. 8-CTA software barrier: padded counter, red.release +
//   pure ld.acquire spin (no nanosleep), next pre prefetched under the barrier.
// =================================================================================
__global__ __launch_bounds__(512) void recur_kernel(
    const float* __restrict__ Wf, const float* __restrict__ Wb)
{
    __shared__ float s_h[4 * 520];      // [4 batches][512+8]
    __shared__ float s_red[8 * 256];    // [ks][b*64+c]

    const int tid = threadIdx.x;
    const int bx  = blockIdx.x;
    const int dir = bx & 1;
    const int grp = (bx >> 1) & 7;          // batch group 0..7 (4 batches)
    const int sl  = bx >> 4;                // col slice 0..7 (64 cols)
    const int c0  = sl * 64;
    const int bgl = grp * 4;
    const float* W = dir ? Wb : Wf;

    const int c  = tid & 63;                // col within slice
    const int ks = tid >> 6;                // k-split 0..7 (k = ks*64..+63)

    // Wh column (c0+c), k in [ks*64, ks*64+64) -> 32 f32x2 regs
    ull wreg[16][2];
    #pragma unroll
    for (int j = 0; j < 16; ++j) {
        int k = ks * 64 + j * 4;
        const float* wp = W + (size_t)(512 + k) * 512 + c0 + c;
        wreg[j][0] = packab(wp[0],    wp[512]);
        wreg[j][1] = packab(wp[1024], wp[1536]);
    }

    // staging: 512 float4s, one per thread
    const int sb   = tid >> 7;              // batch row 0..3
    const int soff = (tid & 127) * 4;       // float offset in 512-row

    // reduce/store map (tid < 256): batch rb, col rc
    const int rb = tid >> 6;
    const int rc = tid & 63;

    unsigned int* bar = &g_bar[(dir * 8 + grp) * 32];

    // first step's pre-activation
    float pre = 0.f;
    {
        const int t0 = dir ? 511 : 0;
        if (tid < 256)
            pre = __ldcg(&g_pre[((size_t)dir * 512 + t0) * 16384 +
                                (size_t)(bgl + rb) * 512 + c0 + rc]);
    }

    for (int s = 0; s < 512; ++s) {
        const int t = dir ? (511 - s) : s;

        float hval = 0.f;
        if (s == 0) {
            if (tid < 256) hval = tanhf(pre);
        } else {
            const int tp = dir ? (t + 1) : (t - 1);
            const float* hbase = g_hs + (size_t)tp * 32 * 1024 +
                                 (size_t)bgl * 1024 + dir * 512;

            // stage the group's 4 h rows (8KB) in one shot
            float4 v0 = __ldcg((const float4*)(hbase + sb * 1024 + soff));
            *(float4*)&s_h[sb * 520 + soff] = v0;
            __syncthreads();

            // mat-vec partials: smem reads warp-broadcast (address = f(b,ks) only)
            ull acc[4];
            #pragma unroll
            for (int b = 0; b < 4; ++b) acc[b] = 0ull;
            #pragma unroll
            for (int b = 0; b < 4; ++b) {
                const ulonglong2* hp = (const ulonglong2*)&s_h[b * 520 + ks * 64];
                #pragma unroll
                for (int j = 0; j < 16; ++j) {
                    ulonglong2 h2 = hp[j];
                    acc[b] = ffma2(h2.x, wreg[j][0], acc[b]);
                    acc[b] = ffma2(h2.y, wreg[j][1], acc[b]);
                }
            }
            #pragma unroll
            for (int b = 0; b < 4; ++b) {
                float2 p = unpack2(acc[b]);
                s_red[ks * 256 + b * 64 + c] = p.x + p.y;
            }
            __syncthreads();

            if (tid < 256) {
                float sum = pre;
                #pragma unroll
                for (int k8 = 0; k8 < 8; ++k8) sum += s_red[k8 * 256 + tid];
                hval = tanhf(sum);
            }
        }

        if (tid < 256)
            __stcg(&g_hs[((size_t)t * 32 + bgl + rb) * 1024 +
                         dir * 512 + c0 + rc], hval);

        if (s < 511) {
            __syncthreads();   // CTA-HB: all h stores ordered before thread0's release
            if (tid == 0)
                asm volatile("red.release.gpu.global.add.u32 [%0], 1;"
                             :: "l"(bar) : "memory");
            // prefetch next step's pre under the barrier
            const int tn = dir ? (510 - s) : (s + 1);
            float npre = 0.f;
            if (tid < 256)
                npre = __ldcg(&g_pre[((size_t)dir * 512 + tn) * 16384 +
                                     (size_t)(bgl + rb) * 512 + c0 + rc]);
            if (tid == 0) {
                const unsigned target = (unsigned)(s + 1) * 8u;
                unsigned v;
                for (;;) {
                    asm volatile("ld.acquire.gpu.global.u32 %0, [%1];"
                                 : "=r"(v) : "l"(bar) : "memory");
                    if (v >= target) break;
                }
            }
            __syncthreads();
            pre = npre;
        }
    }
}

// =================================================================================
// Kernel 3: output GEMM (R4 version: double-buffered smem)
// =================================================================================
__global__ __launch_bounds__(256) void out_gemm(
    const float* __restrict__ Wo, const float* __restrict__ bo,
    float* __restrict__ out)
{
    __shared__ float As[2][8][132];
    __shared__ float Bs[2][8][136];

    const int tid = threadIdx.x;
    const int m0 = blockIdx.y * 128;
    const int n0 = blockIdx.x * 128;

    const int ar  = tid >> 1;
    const int akq = (tid & 1) * 4;
    const float* Arow = g_hs + (size_t)(m0 + ar) * 1024;

    const int bkk = tid >> 5;
    const int bnq = (tid & 31) * 4;

    const int ty = tid >> 4;
    const int tx = tid & 15;

    ull acc[4][8];
    #pragma unroll
    for (int i = 0; i < 4; ++i)
        #pragma unroll
        for (int j = 0; j < 8; ++j) acc[i][j] = 0ull;

    {
        float4 av = *(const float4*)(Arow + akq);
        float4 bv = *(const float4*)(Wo + (size_t)bkk * 512 + n0 + bnq);
        As[0][akq + 0][ar] = av.x;
        As[0][akq + 1][ar] = av.y;
        As[0][akq + 2][ar] = av.z;
        As[0][akq + 3][ar] = av.w;
        *(float4*)&Bs[0][bkk][bnq] = bv;
    }
    __syncthreads();

    int buf = 0;
    for (int k0 = 0; k0 < 1024; k0 += 8) {
        float4 av, bv;
        const bool more = (k0 + 8 < 1024);
        if (more) {
            av = *(const float4*)(Arow + k0 + 8 + akq);
            bv = *(const float4*)(Wo + (size_t)(k0 + 8 + bkk) * 512 + n0 + bnq);
        }

        #pragma unroll
        for (int k = 0; k < 8; ++k) {
            ulonglong2 a01 = *(const ulonglong2*)&As[buf][k][ty * 8];
            ulonglong2 a23 = *(const ulonglong2*)&As[buf][k][ty * 8 + 4];
            float4 bA = *(const float4*)&Bs[buf][k][tx * 8];
            float4 bB = *(const float4*)&Bs[buf][k][tx * 8 + 4];
            ull bd[8];
            bd[0] = pack2(bA.x); bd[1] = pack2(bA.y);
            bd[2] = pack2(bA.z); bd[3] = pack2(bA.w);
            bd[4] = pack2(bB.x); bd[5] = pack2(bB.y);
            bd[6] = pack2(bB.z); bd[7] = pack2(bB.w);
            #pragma unroll
            for (int j = 0; j < 8; ++j) {
                acc[0][j] = ffma2(a01.x, bd[j], acc[0][j]);
                acc[1][j] = ffma2(a01.y, bd[j], acc[1][j]);
                acc[2][j] = ffma2(a23.x, bd[j], acc[2][j]);
                acc[3][j] = ffma2(a23.y, bd[j], acc[3][j]);
            }
        }

        if (more) {
            int nb = buf ^ 1;
            As[nb][akq + 0][ar] = av.x;
            As[nb][akq + 1][ar] = av.y;
            As[nb][akq + 2][ar] = av.z;
            As[nb][akq + 3][ar] = av.w;
            *(float4*)&Bs[nb][bkk][bnq] = bv;
            __syncthreads();
            buf = nb;
        }
    }

    const int og = n0 + tx * 8;
    float4 bl = *(const float4*)(bo + og);
    float4 bh = *(const float4*)(bo + og + 4);
    #pragma unroll
    for (int mp = 0; mp < 4; ++mp) {
        float2 v[8];
        #pragma unroll
        for (int j = 0; j < 8; ++j) v[j] = unpack2(acc[mp][j]);
        #pragma unroll
        for (int p = 0; p < 2; ++p) {
            int m = m0 + ty * 8 + mp * 2 + p;
            int tt = m >> 5, bb2 = m & 31;
            float* dst = out + ((size_t)bb2 * 512 + tt) * 512 + og;
            float4 o0, o1;
            o0.x = (p ? v[0].y : v[0].x) + bl.x;
            o0.y = (p ? v[1].y : v[1].x) + bl.y;
            o0.z = (p ? v[2].y : v[2].x) + bl.z;
            o0.w = (p ? v[3].y : v[3].x) + bl.w;
            o1.x = (p ? v[4].y : v[4].x) + bh.x;
            o1.y = (p ? v[5].y : v[5].x) + bh.y;
            o1.z = (p ? v[6].y : v[6].x) + bh.z;
            o1.w = (p ? v[7].y : v[7].x) + bh.w;
            *(float4*)dst = o0;
            *(float4*)(dst + 4) = o1;
        }
    }
}

// =================================================================================
extern "C" void kernel_launch(void* const* d_in, const int* in_sizes, int n_in,
                              void* d_out, int out_size)
{
    const float* X  = (const float*)d_in[0];
    const float* Wf = (const float*)d_in[1];
    const float* bf = (const float*)d_in[2];
    const float* Wb = (const float*)d_in[3];
    const float* bb = (const float*)d_in[4];
    const float* Wo = (const float*)d_in[5];
    const float* bo = (const float*)d_in[6];
    float* out = (float*)d_out;

    pre_gemm<<<dim3(8, 128), 256>>>(X, Wf, bf, Wb, bb);
    recur_kernel<<<128, 512>>>(Wf, Wb);
    out_gemm<<<dim3(4, 128), 256>>>(Wo, bo, out);
}